// round 2
// baseline (speedup 1.0000x reference)
#include <cuda_runtime.h>
#include <cuda_bf16.h>
#include <cstdio>

// Problem constants
#define N_ATOMS 50000
#define N_BONDS 100000
#define MAX_NB  6
#define F_ATOM  133
#define F_BOND  147
#define HID     600
#define DEPTH   6

// Padded leading dims (multiples of 4 floats => 16B aligned rows)
#define FB_LDA  152   // f_bonds padded 147 -> 152
#define CAT_LDA 736   // concat padded 733 -> 736

// ---------------------------------------------------------------------------
// Scratch (device globals; no allocation allowed)
// ---------------------------------------------------------------------------
__device__ float g_fbp [(size_t)N_BONDS * FB_LDA];   //  60.8 MB padded f_bonds
__device__ float g_inp [(size_t)N_BONDS * HID];      // 240 MB  inp = f_bonds@W_i
__device__ float g_bufA[(size_t)N_BONDS * HID];      // 240 MB  pre-activation msgs
__device__ float g_bufB[(size_t)N_BONDS * HID];      // 240 MB
__device__ float g_amsg[(size_t)N_ATOMS * HID];      // 120 MB  per-atom sums
__device__ float g_cat [(size_t)N_ATOMS * CAT_LDA];  // 147 MB  [f_atoms | a_msg]

#define BM 128
#define BN 128
#define BK 8

// ---------------------------------------------------------------------------
// Generic SGEMM: C[M,N] = A[M,K] @ B[K,N] (+addm) (+bias) (relu)
// BM=BN=128, BK=8, 256 threads, 8x8 per-thread tile (4+4 split for LDS.128).
// A rows must be 16B aligned (lda % 4 == 0) and K padded to 8 with zeros.
// B is bounds-checked (zero-filled).
// ---------------------------------------------------------------------------
template<bool HAS_ADD, bool HAS_BIAS, bool RELU>
__global__ __launch_bounds__(256)
void sgemm128(const float* __restrict__ A, int lda,
              const float* __restrict__ B, int ldb,
              float* __restrict__ C, int ldc,
              int M, int N, int K,
              const float* __restrict__ addm,
              const float* __restrict__ bias)
{
    __shared__ float As[BK][BM];
    __shared__ float Bs[BK][BN];

    const int tid = threadIdx.x;
    const int bx = blockIdx.x, by = blockIdx.y;
    const int tx = tid & 15, ty = tid >> 4;

    const int row0 = by * BM;
    const int col0 = bx * BN;

    const int arow = tid >> 1;         // 0..127
    const int acol = (tid & 1) * 4;    // 0 or 4
    const int brow = tid >> 5;         // 0..7
    const int bcol = (tid & 31) * 4;   // 0..124

    const int rA0 = ty * 4, rA1 = 64 + ty * 4;
    const int cB0 = tx * 4, cB1 = 64 + tx * 4;

    float acc[8][8];
    #pragma unroll
    for (int i = 0; i < 8; i++)
        #pragma unroll
        for (int j = 0; j < 8; j++) acc[i][j] = 0.f;

    for (int k0 = 0; k0 < K; k0 += BK) {
        {   // A tile
            const int gr = row0 + arow;
            float4 v = make_float4(0.f, 0.f, 0.f, 0.f);
            if (gr < M)
                v = *reinterpret_cast<const float4*>(A + (size_t)gr * lda + k0 + acol);
            As[acol + 0][arow] = v.x;
            As[acol + 1][arow] = v.y;
            As[acol + 2][arow] = v.z;
            As[acol + 3][arow] = v.w;
        }
        {   // B tile
            const int gk = k0 + brow;
            const int gc = col0 + bcol;
            float4 v = make_float4(0.f, 0.f, 0.f, 0.f);
            if (gk < K && gc + 3 < N)
                v = *reinterpret_cast<const float4*>(B + (size_t)gk * ldb + gc);
            else if (gk < K) {
                float t[4] = {0.f, 0.f, 0.f, 0.f};
                #pragma unroll
                for (int i = 0; i < 4; i++) if (gc + i < N) t[i] = B[(size_t)gk * ldb + gc + i];
                v = make_float4(t[0], t[1], t[2], t[3]);
            }
            *reinterpret_cast<float4*>(&Bs[brow][bcol]) = v;
        }
        __syncthreads();

        #pragma unroll
        for (int k = 0; k < BK; k++) {
            float a[8], b[8];
            *reinterpret_cast<float4*>(&a[0]) = *reinterpret_cast<const float4*>(&As[k][rA0]);
            *reinterpret_cast<float4*>(&a[4]) = *reinterpret_cast<const float4*>(&As[k][rA1]);
            *reinterpret_cast<float4*>(&b[0]) = *reinterpret_cast<const float4*>(&Bs[k][cB0]);
            *reinterpret_cast<float4*>(&b[4]) = *reinterpret_cast<const float4*>(&Bs[k][cB1]);
            #pragma unroll
            for (int i = 0; i < 8; i++)
                #pragma unroll
                for (int j = 0; j < 8; j++)
                    acc[i][j] += a[i] * b[j];
        }
        __syncthreads();
    }

    #pragma unroll
    for (int i = 0; i < 8; i++) {
        const int r = row0 + (i < 4 ? rA0 + i : rA1 + i - 4);
        if (r >= M) continue;
        #pragma unroll
        for (int j = 0; j < 8; j++) {
            const int c = col0 + (j < 4 ? cB0 + j : cB1 + j - 4);
            if (c >= N) continue;
            float v = acc[i][j];
            if (HAS_ADD)  v += addm[(size_t)r * ldc + c];
            if (HAS_BIAS) v += bias[c];
            if (RELU)     v = fmaxf(v, 0.f);
            C[(size_t)r * ldc + c] = v;
        }
    }
}

// ---------------------------------------------------------------------------
// Fused message-update GEMM:
//   C[b,:] = inp[b,:] + ( amsg[b2a[b],:] - relu(pre[b2revb[b],:]) ) @ W_h
// The x operand is built on the fly inside the A-tile loader (never
// materialized in HBM). M = N_BONDS, N = K = HID.
// ---------------------------------------------------------------------------
__global__ __launch_bounds__(256)
void sgemm128_fusedx(const float* __restrict__ amsg,
                     const float* __restrict__ pre,
                     const int*   __restrict__ b2a,
                     const int*   __restrict__ b2revb,
                     const float* __restrict__ B,     // W_h [HID, HID]
                     const float* __restrict__ addm,  // inp
                     float* __restrict__ C)
{
    __shared__ float As[BK][BM];
    __shared__ float Bs[BK][BN];

    const int tid = threadIdx.x;
    const int bx = blockIdx.x, by = blockIdx.y;
    const int tx = tid & 15, ty = tid >> 4;

    const int row0 = by * BM;
    const int col0 = bx * BN;

    const int arow = tid >> 1;
    const int acol = (tid & 1) * 4;
    const int brow = tid >> 5;
    const int bcol = (tid & 31) * 4;

    const int rA0 = ty * 4, rA1 = 64 + ty * 4;
    const int cB0 = tx * 4, cB1 = 64 + tx * 4;

    // Per-thread gathered row bases (fixed across k-loop)
    const int gr = row0 + arow;
    const float* srcA = nullptr;   // amsg row
    const float* srcR = nullptr;   // reverse pre row
    if (gr < N_BONDS) {
        srcA = amsg + (size_t)b2a[gr]    * HID;
        srcR = pre  + (size_t)b2revb[gr] * HID;
    }

    float acc[8][8];
    #pragma unroll
    for (int i = 0; i < 8; i++)
        #pragma unroll
        for (int j = 0; j < 8; j++) acc[i][j] = 0.f;

    for (int k0 = 0; k0 < HID; k0 += BK) {
        {   // A tile: x = amsg_row - relu(pre_rev_row), built on the fly
            float4 v = make_float4(0.f, 0.f, 0.f, 0.f);
            if (srcA) {
                const float4 m = *reinterpret_cast<const float4*>(srcA + k0 + acol);
                const float4 r = *reinterpret_cast<const float4*>(srcR + k0 + acol);
                v.x = m.x - fmaxf(r.x, 0.f);
                v.y = m.y - fmaxf(r.y, 0.f);
                v.z = m.z - fmaxf(r.z, 0.f);
                v.w = m.w - fmaxf(r.w, 0.f);
            }
            As[acol + 0][arow] = v.x;
            As[acol + 1][arow] = v.y;
            As[acol + 2][arow] = v.z;
            As[acol + 3][arow] = v.w;
        }
        {   // B tile (W_h is HID x HID, HID % 4 == 0; guard N edge)
            const int gk = k0 + brow;
            const int gc = col0 + bcol;
            float4 v = make_float4(0.f, 0.f, 0.f, 0.f);
            if (gc + 3 < HID)
                v = *reinterpret_cast<const float4*>(B + (size_t)gk * HID + gc);
            *reinterpret_cast<float4*>(&Bs[brow][bcol]) = v;
        }
        __syncthreads();

        #pragma unroll
        for (int k = 0; k < BK; k++) {
            float a[8], b[8];
            *reinterpret_cast<float4*>(&a[0]) = *reinterpret_cast<const float4*>(&As[k][rA0]);
            *reinterpret_cast<float4*>(&a[4]) = *reinterpret_cast<const float4*>(&As[k][rA1]);
            *reinterpret_cast<float4*>(&b[0]) = *reinterpret_cast<const float4*>(&Bs[k][cB0]);
            *reinterpret_cast<float4*>(&b[4]) = *reinterpret_cast<const float4*>(&Bs[k][cB1]);
            #pragma unroll
            for (int i = 0; i < 8; i++)
                #pragma unroll
                for (int j = 0; j < 8; j++)
                    acc[i][j] += a[i] * b[j];
        }
        __syncthreads();
    }

    // Epilogue: C = inp + acc (pre-activation; relu applied by readers)
    #pragma unroll
    for (int i = 0; i < 8; i++) {
        const int r = row0 + (i < 4 ? rA0 + i : rA1 + i - 4);
        if (r >= N_BONDS) continue;
        #pragma unroll
        for (int j = 0; j < 8; j++) {
            const int c = col0 + (j < 4 ? cB0 + j : cB1 + j - 4);
            if (c >= HID) continue;
            C[(size_t)r * HID + c] = acc[i][j] + addm[(size_t)r * HID + c];
        }
    }
}

// ---------------------------------------------------------------------------
// a_message[a,:] = sum_k relu(pre[a2b[a,k],:])   (relu applied at read)
// ---------------------------------------------------------------------------
__global__ void gather_sum_kernel(const float4* __restrict__ pre,
                                  const int* __restrict__ a2b,
                                  float4* __restrict__ amsg)
{
    const int idx = blockIdx.x * blockDim.x + threadIdx.x;
    const int total = N_ATOMS * (HID / 4);
    if (idx >= total) return;
    const int a = idx / (HID / 4);
    const int j = idx % (HID / 4);
    float4 s = make_float4(0.f, 0.f, 0.f, 0.f);
    #pragma unroll
    for (int k = 0; k < MAX_NB; k++) {
        const int b = a2b[a * MAX_NB + k];
        const float4 v = pre[(size_t)b * (HID / 4) + j];
        s.x += fmaxf(v.x, 0.f);
        s.y += fmaxf(v.y, 0.f);
        s.z += fmaxf(v.z, 0.f);
        s.w += fmaxf(v.w, 0.f);
    }
    amsg[(size_t)a * (HID / 4) + j] = s;
}

// ---------------------------------------------------------------------------
// pad f_bonds [B,147] -> [B,152] (zero pad)
// ---------------------------------------------------------------------------
__global__ void pad_fbonds_kernel(const float* __restrict__ fb, float* __restrict__ fbp)
{
    const int idx = blockIdx.x * blockDim.x + threadIdx.x;
    const int total = N_BONDS * FB_LDA;
    if (idx >= total) return;
    const int b = idx / FB_LDA;
    const int k = idx % FB_LDA;
    fbp[idx] = (k < F_BOND) ? fb[(size_t)b * F_BOND + k] : 0.f;
}

// ---------------------------------------------------------------------------
// cat[a,:] = [f_atoms[a,:133] | a_message[a,:600] | 0 pad]  (736 wide)
// ---------------------------------------------------------------------------
__global__ void cat_kernel(const float* __restrict__ fa,
                           const float* __restrict__ am,
                           float* __restrict__ cat)
{
    const int idx = blockIdx.x * blockDim.x + threadIdx.x;
    const int total = N_ATOMS * CAT_LDA;
    if (idx >= total) return;
    const int a = idx / CAT_LDA;
    const int k = idx % CAT_LDA;
    float v = 0.f;
    if (k < F_ATOM)               v = fa[(size_t)a * F_ATOM + k];
    else if (k < F_ATOM + HID)    v = am[(size_t)a * HID + (k - F_ATOM)];
    cat[idx] = v;
}

// ---------------------------------------------------------------------------
// launch
// ---------------------------------------------------------------------------
extern "C" void kernel_launch(void* const* d_in, const int* in_sizes, int n_in,
                              void* d_out, int out_size)
{
    const float* f_atoms = (const float*)d_in[0];
    const float* f_bonds = (const float*)d_in[1];
    const int*   a2b     = (const int*)  d_in[2];
    const int*   b2a     = (const int*)  d_in[3];
    const int*   b2revb  = (const int*)  d_in[4];
    const float* W_i     = (const float*)d_in[5];
    const float* W_h     = (const float*)d_in[6];
    const float* W_o     = (const float*)d_in[7];
    const float* b_o     = (const float*)d_in[8];
    float* out = (float*)d_out;

    float *fbp, *inp, *bufA, *bufB, *amsg, *cat;
    cudaGetSymbolAddress((void**)&fbp,  g_fbp);
    cudaGetSymbolAddress((void**)&inp,  g_inp);
    cudaGetSymbolAddress((void**)&bufA, g_bufA);
    cudaGetSymbolAddress((void**)&bufB, g_bufB);
    cudaGetSymbolAddress((void**)&amsg, g_amsg);
    cudaGetSymbolAddress((void**)&cat,  g_cat);

    const int TPB = 256;

    // 1) pad f_bonds
    pad_fbonds_kernel<<<(N_BONDS * FB_LDA + TPB - 1) / TPB, TPB>>>(f_bonds, fbp);

    // 2) inp = f_bonds @ W_i   [100000 x 600], K=147 (padded 152)
    {
        dim3 grid((HID + BN - 1) / BN, (N_BONDS + BM - 1) / BM);
        sgemm128<false, false, false><<<grid, 256>>>(
            fbp, FB_LDA, W_i, HID, inp, HID, N_BONDS, HID, F_BOND, nullptr, nullptr);
    }

    // 3) message-passing iterations (pre-activation buffers; relu on read;
    //    x built inside the GEMM A-loader — never materialized)
    const float* pre = inp;
    float* ping[2] = { bufA, bufB };
    const int gatherBlocks = (N_ATOMS * (HID / 4) + TPB - 1) / TPB;
    dim3 gridH((HID + BN - 1) / BN, (N_BONDS + BM - 1) / BM);

    for (int t = 0; t < DEPTH - 1; t++) {
        float* nxt = ping[t & 1];
        gather_sum_kernel<<<gatherBlocks, TPB>>>((const float4*)pre, a2b, (float4*)amsg);
        sgemm128_fusedx<<<gridH, 256>>>(amsg, pre, b2a, b2revb, W_h, inp, nxt);
        pre = nxt;
    }

    // 4) final gather
    gather_sum_kernel<<<gatherBlocks, TPB>>>((const float4*)pre, a2b, (float4*)amsg);

    // 5) concat [f_atoms | a_message] -> cat (padded to 736)
    cat_kernel<<<(N_ATOMS * CAT_LDA + TPB - 1) / TPB, TPB>>>(f_atoms, amsg, cat);

    // 6) out = relu(cat @ W_o + b_o)   [50000 x 600], K=733 (padded 736)
    {
        dim3 grid((HID + BN - 1) / BN, (N_ATOMS + BM - 1) / BM);
        sgemm128<false, true, true><<<grid, 256>>>(
            cat, CAT_LDA, W_o, HID, out, HID, N_ATOMS, HID, F_ATOM + HID, nullptr, b_o);
    }
}

// round 6
// speedup vs baseline: 1.1094x; 1.1094x over previous
#include <cuda_runtime.h>
#include <cstdint>

// ---------------------------------------------------------------------------
// Problem constants
// ---------------------------------------------------------------------------
#define N_ATOMS 50000
#define N_BONDS 100000
#define MAX_NB  6
#define F_ATOM  133
#define F_BOND  147
#define HID     600
#define DEPTH   6

// K paddings (multiples of BK=16)
#define FB_PAD  160   // 147 -> 160  (10 chunks)
#define WH_PAD  608   // 600 -> 608  (38 chunks)
#define CAT_PAD 736   // 733 -> 736  (46 chunks)
#define NPAD    640   // weight N padded 600 -> 640 (5 col-blocks of 128)

// GEMM tiling
#define BM 128
#define BN 128
#define BK 16
#define SSTR 136                    // smem row stride in floats (8 mod 32)
#define TILEF  (BK * SSTR)          // 2176 floats per buffer
#define STAGEF (4 * TILEF)          // Ah, Al, Bh, Bl
#define SMEM_BYTES (2 * STAGEF * 4) // 69632 B (double buffered)

// ---------------------------------------------------------------------------
// Scratch (device globals; no allocation allowed)
// ---------------------------------------------------------------------------
__device__ float g_fbp [(size_t)N_BONDS * FB_PAD];
__device__ float g_inp [(size_t)N_BONDS * HID];
__device__ float g_bufA[(size_t)N_BONDS * HID];
__device__ float g_bufB[(size_t)N_BONDS * HID];
__device__ float g_amsg[(size_t)N_ATOMS * HID];
__device__ float g_cat [(size_t)N_ATOMS * CAT_PAD];
// tf32-split weights, [Kpad][NPAD], zero padded
__device__ float g_Wi_hi[(size_t)FB_PAD  * NPAD], g_Wi_lo[(size_t)FB_PAD  * NPAD];
__device__ float g_Wh_hi[(size_t)WH_PAD  * NPAD], g_Wh_lo[(size_t)WH_PAD  * NPAD];
__device__ float g_Wo_hi[(size_t)CAT_PAD * NPAD], g_Wo_lo[(size_t)CAT_PAD * NPAD];

// ---------------------------------------------------------------------------
// helpers
// ---------------------------------------------------------------------------
__device__ __forceinline__ float tf32r(float x) {
    uint32_t u;
    asm("cvt.rna.tf32.f32 %0, %1;" : "=r"(u) : "f"(x));
    return __uint_as_float(u);
}

#define MMA_T(d, a, b) \
    asm volatile( \
        "mma.sync.aligned.m16n8k8.row.col.f32.tf32.tf32.f32 " \
        "{%0,%1,%2,%3}, {%4,%5,%6,%7}, {%8,%9}, {%0,%1,%2,%3};" \
        : "+f"((d)[0]), "+f"((d)[1]), "+f"((d)[2]), "+f"((d)[3]) \
        : "r"((a)[0]), "r"((a)[1]), "r"((a)[2]), "r"((a)[3]), \
          "r"((b)[0]), "r"((b)[1]))

// ---------------------------------------------------------------------------
// tf32 3x MMA GEMM: C[M,600] = A[M,K] @ W[K,600] (+addm)(+bias)(relu)
// MODE 0: C = acc                (W_i)
// MODE 1: A row r = amsg[b2a[r]] - relu(pre[b2revb[r]]); C = acc + addm (W_h)
// MODE 2: C = relu(acc + bias)   (W_o)
// ---------------------------------------------------------------------------
template<int MODE>
__global__ __launch_bounds__(256, 1)
void mma_gemm(const float* __restrict__ A, int lda, int M, int KC,
              const float* __restrict__ Bhi, const float* __restrict__ Blo,
              const float* __restrict__ amsg, const float* __restrict__ pre,
              const int* __restrict__ b2a, const int* __restrict__ b2revb,
              const float* __restrict__ addm, const float* __restrict__ bias,
              float* __restrict__ C)
{
    extern __shared__ float sm[];
    const int tid  = threadIdx.x;
    const int lane = tid & 31;
    const int wid  = tid >> 5;
    const int wm   = wid >> 2;       // 0..1
    const int wn   = wid & 3;        // 0..3
    const int lrow = lane >> 2;      // 0..7
    const int lk   = lane & 3;       // 0..3
    const int row0 = blockIdx.y * BM;
    const int col0 = blockIdx.x * BN;

    // ---- per-thread staging slots ----
    // A: 2 slots, each one float4 of a row's K segment
    int arow[2], akq[2];
    bool aval[2];
    const float* pAm[2];
    const float* pRe[2];
    #pragma unroll
    for (int i = 0; i < 2; i++) {
        const int slot = tid + i * 256;
        arow[i] = slot >> 2;
        akq[i]  = slot & 3;
        const int gr = row0 + arow[i];
        aval[i] = (gr < M);
        if (MODE == 1) {
            const int ga = aval[i] ? b2a[gr]    : 0;
            const int gb = aval[i] ? b2revb[gr] : 0;
            pAm[i] = amsg + (size_t)ga * HID + akq[i] * 4;
            pRe[i] = pre  + (size_t)gb * HID + akq[i] * 4;
        } else {
            pAm[i] = A + (size_t)(aval[i] ? gr : 0) * lda + akq[i] * 4;
            pRe[i] = nullptr;
        }
    }
    // B: 2 slots, each one float4 of [k][n]
    int bkr[2], bnq[2];
    #pragma unroll
    for (int i = 0; i < 2; i++) {
        const int slot = tid + i * 256;
        bkr[i] = slot >> 5;   // 0..15
        bnq[i] = slot & 31;   // 0..31
    }

    float acc[4][4][4];
    #pragma unroll
    for (int mt = 0; mt < 4; mt++)
        #pragma unroll
        for (int nt = 0; nt < 4; nt++)
            #pragma unroll
            for (int j = 0; j < 4; j++) acc[mt][nt][j] = 0.f;

    float4 fa[2], fq[2], fbh[2], fbl[2];

    // ---- fetch chunk 0 ----
    #pragma unroll
    for (int i = 0; i < 2; i++) {
        fa[i] = make_float4(0.f, 0.f, 0.f, 0.f);
        fq[i] = make_float4(0.f, 0.f, 0.f, 0.f);
        const bool kok = (MODE != 1) || (akq[i] * 4 < HID);
        if (aval[i] && kok) {
            fa[i] = *(const float4*)(pAm[i]);
            if (MODE == 1) fq[i] = *(const float4*)(pRe[i]);
        }
        const size_t bo = (size_t)bkr[i] * NPAD + col0 + bnq[i] * 4;
        fbh[i] = *(const float4*)(Bhi + bo);
        fbl[i] = *(const float4*)(Blo + bo);
    }

    // ---- store stage 0 ----
    {
        float* Ah = sm;
        float* Al = Ah + TILEF;
        float* Bh = Al + TILEF;
        float* Bl = Bh + TILEF;
        #pragma unroll
        for (int i = 0; i < 2; i++) {
            float x[4];
            if (MODE == 1) {
                x[0] = fa[i].x - fmaxf(fq[i].x, 0.f);
                x[1] = fa[i].y - fmaxf(fq[i].y, 0.f);
                x[2] = fa[i].z - fmaxf(fq[i].z, 0.f);
                x[3] = fa[i].w - fmaxf(fq[i].w, 0.f);
            } else { x[0]=fa[i].x; x[1]=fa[i].y; x[2]=fa[i].z; x[3]=fa[i].w; }
            const int base = akq[i] * 4 * SSTR + arow[i];
            #pragma unroll
            for (int j = 0; j < 4; j++) {
                const float h = tf32r(x[j]);
                Ah[base + j * SSTR] = h;
                Al[base + j * SSTR] = tf32r(x[j] - h);
            }
            const int bb = bkr[i] * SSTR + bnq[i] * 4;
            *(float4*)(Bh + bb) = fbh[i];
            *(float4*)(Bl + bb) = fbl[i];
        }
    }
    __syncthreads();

    // ---- main loop ----
    for (int c = 0; c < KC; c++) {
        const bool hasNext = (c + 1 < KC);
        const int k0n = (c + 1) * BK;

        if (hasNext) {
            #pragma unroll
            for (int i = 0; i < 2; i++) {
                fa[i] = make_float4(0.f, 0.f, 0.f, 0.f);
                fq[i] = make_float4(0.f, 0.f, 0.f, 0.f);
                const bool kok = (MODE != 1) || (k0n + akq[i] * 4 < HID);
                if (aval[i] && kok) {
                    fa[i] = *(const float4*)(pAm[i] + k0n);
                    if (MODE == 1) fq[i] = *(const float4*)(pRe[i] + k0n);
                }
                const size_t bo = (size_t)(k0n + bkr[i]) * NPAD + col0 + bnq[i] * 4;
                fbh[i] = *(const float4*)(Bhi + bo);
                fbl[i] = *(const float4*)(Blo + bo);
            }
        }

        // compute current stage
        {
            const float* Ah = sm + (c & 1) * STAGEF;
            const float* Al = Ah + TILEF;
            const float* Bh = Al + TILEF;
            const float* Bl = Bh + TILEF;

            #pragma unroll
            for (int k8 = 0; k8 < 2; k8++) {
                const int kb = k8 * 8 + lk;
                uint32_t ah[4][4], al[4][4], bh[4][2], bl[4][2];
                #pragma unroll
                for (int mt = 0; mt < 4; mt++) {
                    const int m = wm * 64 + mt * 16 + lrow;
                    ah[mt][0] = __float_as_uint(Ah[kb * SSTR + m]);
                    ah[mt][1] = __float_as_uint(Ah[kb * SSTR + m + 8]);
                    ah[mt][2] = __float_as_uint(Ah[(kb + 4) * SSTR + m]);
                    ah[mt][3] = __float_as_uint(Ah[(kb + 4) * SSTR + m + 8]);
                    al[mt][0] = __float_as_uint(Al[kb * SSTR + m]);
                    al[mt][1] = __float_as_uint(Al[kb * SSTR + m + 8]);
                    al[mt][2] = __float_as_uint(Al[(kb + 4) * SSTR + m]);
                    al[mt][3] = __float_as_uint(Al[(kb + 4) * SSTR + m + 8]);
                }
                #pragma unroll
                for (int nt = 0; nt < 4; nt++) {
                    const int n = wn * 32 + nt * 8 + lrow;
                    bh[nt][0] = __float_as_uint(Bh[kb * SSTR + n]);
                    bh[nt][1] = __float_as_uint(Bh[(kb + 4) * SSTR + n]);
                    bl[nt][0] = __float_as_uint(Bl[kb * SSTR + n]);
                    bl[nt][1] = __float_as_uint(Bl[(kb + 4) * SSTR + n]);
                }
                #pragma unroll
                for (int mt = 0; mt < 4; mt++)
                    #pragma unroll
                    for (int nt = 0; nt < 4; nt++) {
                        MMA_T(acc[mt][nt], ah[mt], bh[nt]);
                        MMA_T(acc[mt][nt], ah[mt], bl[nt]);
                        MMA_T(acc[mt][nt], al[mt], bh[nt]);
                    }
            }
        }

        // store next stage
        if (hasNext) {
            float* Ah = sm + ((c + 1) & 1) * STAGEF;
            float* Al = Ah + TILEF;
            float* Bh = Al + TILEF;
            float* Bl = Bh + TILEF;
            #pragma unroll
            for (int i = 0; i < 2; i++) {
                float x[4];
                if (MODE == 1) {
                    x[0] = fa[i].x - fmaxf(fq[i].x, 0.f);
                    x[1] = fa[i].y - fmaxf(fq[i].y, 0.f);
                    x[2] = fa[i].z - fmaxf(fq[i].z, 0.f);
                    x[3] = fa[i].w - fmaxf(fq[i].w, 0.f);
                } else { x[0]=fa[i].x; x[1]=fa[i].y; x[2]=fa[i].z; x[3]=fa[i].w; }
                const int base = akq[i] * 4 * SSTR + arow[i];
                #pragma unroll
                for (int j = 0; j < 4; j++) {
                    const float h = tf32r(x[j]);
                    Ah[base + j * SSTR] = h;
                    Al[base + j * SSTR] = tf32r(x[j] - h);
                }
                const int bb = bkr[i] * SSTR + bnq[i] * 4;
                *(float4*)(Bh + bb) = fbh[i];
                *(float4*)(Bl + bb) = fbl[i];
            }
        }
        __syncthreads();
    }

    // ---- epilogue ----
    #pragma unroll
    for (int mt = 0; mt < 4; mt++) {
        const int r0 = row0 + wm * 64 + mt * 16 + lrow;
        const int r1 = r0 + 8;
        #pragma unroll
        for (int nt = 0; nt < 4; nt++) {
            const int cc = col0 + wn * 32 + nt * 8 + lk * 2;
            if (cc >= HID) continue;
            float v0 = acc[mt][nt][0], v1 = acc[mt][nt][1];
            float v2 = acc[mt][nt][2], v3 = acc[mt][nt][3];
            if (MODE == 2) {
                const float bs0 = bias[cc], bs1 = bias[cc + 1];
                v0 = fmaxf(v0 + bs0, 0.f); v1 = fmaxf(v1 + bs1, 0.f);
                v2 = fmaxf(v2 + bs0, 0.f); v3 = fmaxf(v3 + bs1, 0.f);
            }
            if (r0 < M) {
                float2 o = make_float2(v0, v1);
                if (MODE == 1) {
                    const float2 a = *(const float2*)(addm + (size_t)r0 * HID + cc);
                    o.x += a.x; o.y += a.y;
                }
                *(float2*)(C + (size_t)r0 * HID + cc) = o;
            }
            if (r1 < M) {
                float2 o = make_float2(v2, v3);
                if (MODE == 1) {
                    const float2 a = *(const float2*)(addm + (size_t)r1 * HID + cc);
                    o.x += a.x; o.y += a.y;
                }
                *(float2*)(C + (size_t)r1 * HID + cc) = o;
            }
        }
    }
}

// ---------------------------------------------------------------------------
// weight pad + tf32 hi/lo split: [K,600] -> hi/lo [Kpad][640]
// ---------------------------------------------------------------------------
__global__ void pad_split_w(const float* __restrict__ W, int K, int Kpad,
                            float* __restrict__ Whi, float* __restrict__ Wlo)
{
    const int idx = blockIdx.x * blockDim.x + threadIdx.x;
    const int total = Kpad * NPAD;
    if (idx >= total) return;
    const int k = idx / NPAD;
    const int n = idx % NPAD;
    const float x = (k < K && n < HID) ? W[(size_t)k * HID + n] : 0.f;
    const float h = tf32r(x);
    Whi[idx] = h;
    Wlo[idx] = tf32r(x - h);
}

// ---------------------------------------------------------------------------
// a_message[a,:] = sum_k relu(pre[a2b[a,k],:])
// ---------------------------------------------------------------------------
__global__ void gather_sum_kernel(const float4* __restrict__ pre,
                                  const int* __restrict__ a2b,
                                  float4* __restrict__ amsg)
{
    const int idx = blockIdx.x * blockDim.x + threadIdx.x;
    const int total = N_ATOMS * (HID / 4);
    if (idx >= total) return;
    const int a = idx / (HID / 4);
    const int j = idx % (HID / 4);
    float4 s = make_float4(0.f, 0.f, 0.f, 0.f);
    #pragma unroll
    for (int k = 0; k < MAX_NB; k++) {
        const int b = a2b[a * MAX_NB + k];
        const float4 v = pre[(size_t)b * (HID / 4) + j];
        s.x += fmaxf(v.x, 0.f);
        s.y += fmaxf(v.y, 0.f);
        s.z += fmaxf(v.z, 0.f);
        s.w += fmaxf(v.w, 0.f);
    }
    amsg[(size_t)a * (HID / 4) + j] = s;
}

__global__ void pad_fbonds_kernel(const float* __restrict__ fb, float* __restrict__ fbp)
{
    const int idx = blockIdx.x * blockDim.x + threadIdx.x;
    const int total = N_BONDS * FB_PAD;
    if (idx >= total) return;
    const int b = idx / FB_PAD;
    const int k = idx % FB_PAD;
    fbp[idx] = (k < F_BOND) ? fb[(size_t)b * F_BOND + k] : 0.f;
}

__global__ void cat_kernel(const float* __restrict__ fa,
                           const float* __restrict__ am,
                           float* __restrict__ cat)
{
    const int idx = blockIdx.x * blockDim.x + threadIdx.x;
    const int total = N_ATOMS * CAT_PAD;
    if (idx >= total) return;
    const int a = idx / CAT_PAD;
    const int k = idx % CAT_PAD;
    float v = 0.f;
    if (k < F_ATOM)            v = fa[(size_t)a * F_ATOM + k];
    else if (k < F_ATOM + HID) v = am[(size_t)a * HID + (k - F_ATOM)];
    cat[idx] = v;
}

// ---------------------------------------------------------------------------
// launch
// ---------------------------------------------------------------------------
extern "C" void kernel_launch(void* const* d_in, const int* in_sizes, int n_in,
                              void* d_out, int out_size)
{
    const float* f_atoms = (const float*)d_in[0];
    const float* f_bonds = (const float*)d_in[1];
    const int*   a2b     = (const int*)  d_in[2];
    const int*   b2a     = (const int*)  d_in[3];
    const int*   b2revb  = (const int*)  d_in[4];
    const float* W_i     = (const float*)d_in[5];
    const float* W_h     = (const float*)d_in[6];
    const float* W_o     = (const float*)d_in[7];
    const float* b_o     = (const float*)d_in[8];
    float* out = (float*)d_out;

    float *fbp, *inp, *bufA, *bufB, *amsg, *cat;
    float *WiH, *WiL, *WhH, *WhL, *WoH, *WoL;
    cudaGetSymbolAddress((void**)&fbp,  g_fbp);
    cudaGetSymbolAddress((void**)&inp,  g_inp);
    cudaGetSymbolAddress((void**)&bufA, g_bufA);
    cudaGetSymbolAddress((void**)&bufB, g_bufB);
    cudaGetSymbolAddress((void**)&amsg, g_amsg);
    cudaGetSymbolAddress((void**)&cat,  g_cat);
    cudaGetSymbolAddress((void**)&WiH,  g_Wi_hi);
    cudaGetSymbolAddress((void**)&WiL,  g_Wi_lo);
    cudaGetSymbolAddress((void**)&WhH,  g_Wh_hi);
    cudaGetSymbolAddress((void**)&WhL,  g_Wh_lo);
    cudaGetSymbolAddress((void**)&WoH,  g_Wo_hi);
    cudaGetSymbolAddress((void**)&WoL,  g_Wo_lo);

    cudaFuncSetAttribute(mma_gemm<0>, cudaFuncAttributeMaxDynamicSharedMemorySize, SMEM_BYTES);
    cudaFuncSetAttribute(mma_gemm<1>, cudaFuncAttributeMaxDynamicSharedMemorySize, SMEM_BYTES);
    cudaFuncSetAttribute(mma_gemm<2>, cudaFuncAttributeMaxDynamicSharedMemorySize, SMEM_BYTES);

    const int TPB = 256;

    // 0) weight prep
    pad_split_w<<<(FB_PAD  * NPAD + TPB - 1) / TPB, TPB>>>(W_i, F_BOND,       FB_PAD,  WiH, WiL);
    pad_split_w<<<(WH_PAD  * NPAD + TPB - 1) / TPB, TPB>>>(W_h, HID,          WH_PAD,  WhH, WhL);
    pad_split_w<<<(CAT_PAD * NPAD + TPB - 1) / TPB, TPB>>>(W_o, F_ATOM + HID, CAT_PAD, WoH, WoL);

    // 1) pad f_bonds
    pad_fbonds_kernel<<<(N_BONDS * FB_PAD + TPB - 1) / TPB, TPB>>>(f_bonds, fbp);

    dim3 gridB(NPAD / BN, (N_BONDS + BM - 1) / BM);   // (5, 782)
    dim3 gridA(NPAD / BN, (N_ATOMS + BM - 1) / BM);   // (5, 391)

    // 2) inp = f_bonds @ W_i  (pre-activation)
    mma_gemm<0><<<gridB, 256, SMEM_BYTES>>>(
        fbp, FB_PAD, N_BONDS, FB_PAD / BK, WiH, WiL,
        nullptr, nullptr, nullptr, nullptr, nullptr, nullptr, inp);

    // 3) message passing
    const float* pre = inp;
    float* ping[2] = { bufA, bufB };
    const int gatherBlocks = (N_ATOMS * (HID / 4) + TPB - 1) / TPB;

    for (int t = 0; t < DEPTH - 1; t++) {
        float* nxt = ping[t & 1];
        gather_sum_kernel<<<gatherBlocks, TPB>>>((const float4*)pre, a2b, (float4*)amsg);
        mma_gemm<1><<<gridB, 256, SMEM_BYTES>>>(
            nullptr, 0, N_BONDS, WH_PAD / BK, WhH, WhL,
            amsg, pre, b2a, b2revb, inp, nullptr, nxt);
        pre = nxt;
    }

    // 4) final gather + concat
    gather_sum_kernel<<<gatherBlocks, TPB>>>((const float4*)pre, a2b, (float4*)amsg);
    cat_kernel<<<(N_ATOMS * CAT_PAD + TPB - 1) / TPB, TPB>>>(f_atoms, amsg, cat);

    // 5) out = relu(cat @ W_o + b_o)
    mma_gemm<2><<<gridA, 256, SMEM_BYTES>>>(
        cat, CAT_PAD, N_ATOMS, CAT_PAD / BK, WoH, WoL,
        nullptr, nullptr, nullptr, nullptr, nullptr, b_o, out);
}